// round 1
// baseline (speedup 1.0000x reference)
#include <cuda_runtime.h>
#include <cstddef>

#define NB   8
#define NN   4096
#define MAXD 256

// ---------------- scratch (device globals; no allocation allowed) ----------------
static __device__ int   g_deg[NN];
static __device__ int   g_col[NN * MAXD];
static __device__ float g_h1[(size_t)NB * NN * 128];
static __device__ float g_x2[(size_t)NB * NN * 128];
static __device__ float g_h2[(size_t)NB * NN * 64];

// ---------------- adjacency build: warp per row, deterministic order -------------
__global__ void __launch_bounds__(256) build_adj(const float* __restrict__ graph)
{
    const int w    = (blockIdx.x * blockDim.x + threadIdx.x) >> 5;  // row 0..4095
    const int lane = threadIdx.x & 31;
    const float* __restrict__ row = graph + (size_t)w * NN;
    int cnt = 0;
    for (int base = 0; base < NN; base += 32) {
        float v = row[base + lane];
        unsigned msk = __ballot_sync(0xffffffffu, v != 0.0f);
        if (v != 0.0f) {
            int idx = cnt + __popc(msk & ((1u << lane) - 1u));
            if (idx < MAXD) g_col[w * MAXD + idx] = base + lane;
        }
        cnt += __popc(msk);
    }
    if (lane == 0) g_deg[w] = cnt < MAXD ? cnt : MAXD;
}

// ---------------- small GEMM: out[r][c] = sum_d x[r][d] * W[c][d] ----------------
template<int DIN, int DOUT, int ROWS>
__device__ __forceinline__ void linear_body(const float* __restrict__ x,
                                            const float* __restrict__ W,
                                            float* __restrict__ out)
{
    __shared__ float xs[ROWS * DIN];
    const int c = threadIdx.x;

    float wr[DIN];
#pragma unroll
    for (int d = 0; d < DIN; d++) wr[d] = W[c * DIN + d];

    const size_t row0 = (size_t)blockIdx.x * ROWS;
    {
        const float4* xg  = reinterpret_cast<const float4*>(x + row0 * DIN);
        float4*       xs4 = reinterpret_cast<float4*>(xs);
        constexpr int T4  = ROWS * DIN / 4;
        for (int i = c; i < T4; i += DOUT) xs4[i] = xg[i];
    }
    __syncthreads();

    for (int r = 0; r < ROWS; r++) {
        const float4* xr = reinterpret_cast<const float4*>(xs + r * DIN);
        float a = 0.f;
#pragma unroll
        for (int d4 = 0; d4 < DIN / 4; d4++) {
            float4 xv = xr[d4];                 // LDS.128 broadcast (conflict-free)
            a = fmaf(xv.x, wr[4 * d4 + 0], a);
            a = fmaf(xv.y, wr[4 * d4 + 1], a);
            a = fmaf(xv.z, wr[4 * d4 + 2], a);
            a = fmaf(xv.w, wr[4 * d4 + 3], a);
        }
        out[(row0 + r) * DOUT + c] = a;
    }
}

__global__ void __launch_bounds__(128) linear1_kernel(const float* __restrict__ x,
                                                      const float* __restrict__ W)
{
    linear_body<64, 128, 64>(x, W, g_h1);
}

__global__ void __launch_bounds__(64) linear2_kernel(const float* __restrict__ W)
{
    linear_body<128, 64, 64>(g_x2, W, g_h2);
}

// ---------------- sparse GAT attention: one warp per (b, n), online softmax -----
template<int H, bool RELU>
__device__ __forceinline__ void attn_body(const float* __restrict__ h,
                                          const float* __restrict__ bias,
                                          float* __restrict__ out)
{
    constexpr int VEC = H / 32;                    // 4 (H=128) or 2 (H=64)
    const int w    = (blockIdx.x * blockDim.x + threadIdx.x) >> 5;
    const int lane = threadIdx.x & 31;
    const int b    = w >> 12;                       // / 4096
    const int n    = w & (NN - 1);
    const float* __restrict__ hb = h + (size_t)b * NN * H;

    float q[VEC];
    {
        const float* qp = hb + n * H + lane * VEC;
        if constexpr (VEC == 4) {
            float4 t = *reinterpret_cast<const float4*>(qp);
            q[0] = t.x; q[1] = t.y; q[2] = t.z; q[3] = t.w;
        } else {
            float2 t = *reinterpret_cast<const float2*>(qp);
            q[0] = t.x; q[1] = t.y;
        }
    }

    float acc[VEC];
#pragma unroll
    for (int k = 0; k < VEC; k++) acc[k] = 0.f;
    float m = -1e30f, l = 0.f;

    const int d = g_deg[n];
    const int* __restrict__ cp = g_col + n * MAXD;

    for (int j0 = 0; j0 < d; j0 += 4) {
        float hv[4][VEC];
        float s[4];
#pragma unroll
        for (int i = 0; i < 4; i++) {
            int jj = j0 + i;
            int jc = jj < d ? jj : d - 1;          // clamp tail (masked below)
            int c  = cp[jc];
            const float* hp = hb + c * H + lane * VEC;
            if constexpr (VEC == 4) {
                float4 t = *reinterpret_cast<const float4*>(hp);
                hv[i][0] = t.x; hv[i][1] = t.y; hv[i][2] = t.z; hv[i][3] = t.w;
            } else {
                float2 t = *reinterpret_cast<const float2*>(hp);
                hv[i][0] = t.x; hv[i][1] = t.y;
            }
            float p = 0.f;
#pragma unroll
            for (int k = 0; k < VEC; k++) p = fmaf(q[k], hv[i][k], p);
            s[i] = p;
        }
        // 4 interleaved butterfly reductions (all lanes end with the full dots)
#pragma unroll
        for (int o = 16; o > 0; o >>= 1) {
#pragma unroll
            for (int i = 0; i < 4; i++) s[i] += __shfl_xor_sync(0xffffffffu, s[i], o);
        }
#pragma unroll
        for (int i = 0; i < 4; i++)
            if (j0 + i >= d) s[i] = -1e30f;        // tail -> exp == 0

        float gm = fmaxf(fmaxf(s[0], s[1]), fmaxf(s[2], s[3]));
        float m1 = fmaxf(m, gm);
        float sc = __expf(m - m1);                  // first iter: exp(-huge) = 0
        float e0 = __expf(s[0] - m1);
        float e1 = __expf(s[1] - m1);
        float e2 = __expf(s[2] - m1);
        float e3 = __expf(s[3] - m1);
        l = fmaf(l, sc, (e0 + e1) + (e2 + e3));
#pragma unroll
        for (int k = 0; k < VEC; k++)
            acc[k] = fmaf(e3, hv[3][k],
                     fmaf(e2, hv[2][k],
                     fmaf(e1, hv[1][k],
                     fmaf(e0, hv[0][k], acc[k] * sc))));
        m = m1;
    }

    const float inv = 1.0f / l;                     // deg >= 1 (self loop) -> l > 0
    float* op = out + ((size_t)(b * NN + n)) * H + lane * VEC;
    float r[VEC];
#pragma unroll
    for (int k = 0; k < VEC; k++) {
        float v = fmaf(acc[k], inv, bias[lane * VEC + k]);
        if constexpr (RELU) v = fmaxf(v, 0.f);
        r[k] = v;
    }
    if constexpr (VEC == 4) {
        float4 t; t.x = r[0]; t.y = r[1]; t.z = r[2]; t.w = r[3];
        *reinterpret_cast<float4*>(op) = t;
    } else {
        float2 t; t.x = r[0]; t.y = r[1];
        *reinterpret_cast<float2*>(op) = t;
    }
}

__global__ void __launch_bounds__(256) attn1_kernel(const float* __restrict__ bias)
{
    attn_body<128, true>(g_h1, bias, g_x2);
}

__global__ void __launch_bounds__(256) attn2_kernel(const float* __restrict__ bias,
                                                    float* __restrict__ out)
{
    attn_body<64, false>(g_h2, bias, out);
}

// ---------------- launch ----------------
extern "C" void kernel_launch(void* const* d_in, const int* in_sizes, int n_in,
                              void* d_out, int out_size)
{
    (void)in_sizes; (void)n_in; (void)out_size;
    const float* x  = (const float*)d_in[0];
    const float* gr = (const float*)d_in[1];
    const float* W1 = (const float*)d_in[2];
    const float* b1 = (const float*)d_in[3];
    const float* W2 = (const float*)d_in[4];
    const float* b2 = (const float*)d_in[5];
    float* out = (float*)d_out;

    build_adj<<<NN / 8, 256>>>(gr);                       // 4096 warps
    linear1_kernel<<<(NB * NN) / 64, 128>>>(x, W1);       // h1 = x @ W1^T
    attn1_kernel<<<(NB * NN) / 8, 256>>>(b1);             // x2 = relu(GAT(h1) + b1)
    linear2_kernel<<<(NB * NN) / 64, 64>>>(W2);           // h2 = x2 @ W2^T
    attn2_kernel<<<(NB * NN) / 8, 256>>>(b2, out);        // out = GAT(h2) + b2
}